// round 1
// baseline (speedup 1.0000x reference)
#include <cuda_runtime.h>

// Correlation layer: out[b, i*41+j, y, x] =
//   (1/576) * sum_c in1[b,c,y,x] * in2[b,c, y-2*(j-10), x-2*(i-10)]
// in1, in2: [4, 64, 96, 160] fp32;  out: [4, 1681, 96, 160] fp32.
//
// CTA = (j, y, b). smem holds in1 row (sA: 64x160) and the zero-padded
// in2 row y' (sB: 64x240 floats = 120 f32-pairs covering x' in [-60,180)).
// 128 threads = 16 x-groups (5 pairs each) x 8 i-groups (6 displacements
// each, covering i in [0,48) with static clamp to i<=40).
// Packed fp32 math via fma.rn.f32x2 (SASS FFMA2) -> 2 MAC/lane/instr.

#define D41 41
#define HH 96
#define WW 160
#define CC 64

#define SA_FLOATS (CC * WW)          // 10240
#define SB_FLOATS (CC * 240)         // 15360
#define SMEM_BYTES ((SA_FLOATS + SB_FLOATS) * 4)   // 102400

__device__ __forceinline__ void fma2(unsigned long long& d,
                                     unsigned long long a,
                                     unsigned long long b) {
    asm("fma.rn.f32x2 %0, %1, %2, %0;" : "+l"(d) : "l"(a), "l"(b));
}

__device__ __forceinline__ unsigned long long lds2(const float* p) {
    return *reinterpret_cast<const unsigned long long*>(p);
}

// FAST: i-group fully in range (i0+5 <= 40), shifts = 5-ii.
// !FAST: i0 == 36 pattern, shifts = {4,3,2,1,0,0}, store only ii<5.
template<bool FAST>
__device__ __forceinline__ void corr_compute_store(
    const float* __restrict__ sA, const float* __restrict__ sB,
    int p0, int i0, int qb,
    float* __restrict__ out, int obase, int ostride_i)
{
    unsigned long long acc[6][5];
#pragma unroll
    for (int ii = 0; ii < 6; ++ii)
#pragma unroll
        for (int k = 0; k < 5; ++k) acc[ii][k] = 0ULL;

    const float* Ar = sA + 2 * p0;
    const float* Br = sB + 2 * qb;

#pragma unroll 2
    for (int c = 0; c < CC; ++c) {
        unsigned long long a[5];
#pragma unroll
        for (int k = 0; k < 5; ++k) a[k] = lds2(Ar + c * WW + 2 * k);
        unsigned long long bw[10];
#pragma unroll
        for (int t = 0; t < 10; ++t) bw[t] = lds2(Br + c * 240 + 2 * t);
#pragma unroll
        for (int ii = 0; ii < 6; ++ii) {
            const int sh = FAST ? (5 - ii) : (ii < 4 ? 4 - ii : 0);
#pragma unroll
            for (int k = 0; k < 5; ++k)
                fma2(acc[ii][k], a[k], bw[sh + k]);
        }
    }

    const float scale = 1.0f / 576.0f;
    const int NI = FAST ? 6 : 5;
#pragma unroll
    for (int ii = 0; ii < 6; ++ii) {
        if (ii >= NI) break;
#pragma unroll
        for (int k = 0; k < 5; ++k) {
            unsigned long long v = acc[ii][k];
            float lo = __uint_as_float((unsigned)(v & 0xffffffffu));
            float hi = __uint_as_float((unsigned)(v >> 32));
            float2 r;
            r.x = lo * scale;
            r.y = hi * scale;
            *reinterpret_cast<float2*>(out + obase + (i0 + ii) * ostride_i
                                       + 2 * (p0 + k)) = r;
        }
    }
}

extern __shared__ float smem[];

__global__ void __launch_bounds__(128)
Correlation_36730560316063_kernel(const float* __restrict__ in1,
                                  const float* __restrict__ in2,
                                  float* __restrict__ out)
{
    const int j = blockIdx.x;      // dy index
    const int y = blockIdx.y;
    const int b = blockIdx.z;
    const int tid = threadIdx.x;

    const int dy = 2 * (j - 10);
    const int y2 = y - dy;

    // out offset for (i=0, x=0): ((b*1681 + 0*41 + j)*96 + y)*160
    const int obase = ((b * (D41 * D41) + j) * HH + y) * WW;
    const int ostride_i = D41 * HH * WW;   // step for i -> i+1 in channel dim

    if (y2 < 0 || y2 >= HH) {
        // entire (b, y, j) slab is zero (output buffer is poisoned: must write)
        const float4 z = make_float4(0.f, 0.f, 0.f, 0.f);
        for (int idx = tid; idx < D41 * (WW / 4); idx += 128) {
            int i = idx / (WW / 4);
            int v = idx % (WW / 4);
            *reinterpret_cast<float4*>(out + obase + i * ostride_i + v * 4) = z;
        }
        return;
    }

    float* sA = smem;               // [64][160]
    float* sB = smem + SA_FLOATS;   // [64][240], cols [0,60)=0, [60,220)=data, [220,240)=0

    // zero pads of sB: 15 + 5 float4 per channel row
    {
        const float4 z = make_float4(0.f, 0.f, 0.f, 0.f);
        for (int idx = tid; idx < CC * 20; idx += 128) {
            int c = idx / 20, v = idx % 20;
            int off = (v < 15) ? v * 4 : 220 + (v - 15) * 4;
            *reinterpret_cast<float4*>(sB + c * 240 + off) = z;
        }
    }
    // sA <- in1[b, :, y, :]
    {
        const float* a_src = in1 + ((b * CC) * HH + y) * WW;
        for (int idx = tid; idx < CC * (WW / 4); idx += 128) {
            int c = idx / (WW / 4), v = idx % (WW / 4);
            *reinterpret_cast<float4*>(sA + c * WW + v * 4) =
                *reinterpret_cast<const float4*>(a_src + c * HH * WW + v * 4);
        }
    }
    // sB data <- in2[b, :, y2, :]
    {
        const float* b_src = in2 + ((b * CC) * HH + y2) * WW;
        for (int idx = tid; idx < CC * (WW / 4); idx += 128) {
            int c = idx / (WW / 4), v = idx % (WW / 4);
            *reinterpret_cast<float4*>(sB + c * 240 + 60 + v * 4) =
                *reinterpret_cast<const float4*>(b_src + c * HH * WW + v * 4);
        }
    }
    __syncthreads();

    const int xg = tid & 15;        // 16 x-groups
    const int ig = tid >> 4;        // 8 i-groups
    const int p0 = xg * 5;          // first output x-pair (x = 2*p0)
    const int i0 = ig * 6;          // first displacement index

    if (ig == 7) return;            // i0=42: all clamped, nothing stored

    // B pair index for (p, i): q = p + 40 - i  (sB pair q covers x' = 2q-60)
    if (ig < 6) {
        const int qb = p0 + 35 - i0;          // window [qb, qb+10)
        corr_compute_store<true>(sA, sB, p0, i0, qb, out, obase, ostride_i);
    } else {                                  // ig == 6, i = 36..41 (41 clamped)
        const int qb = p0;                    // window [p0, p0+9)
        corr_compute_store<false>(sA, sB, p0, i0, qb, out, obase, ostride_i);
    }
}

extern "C" void kernel_launch(void* const* d_in, const int* in_sizes, int n_in,
                              void* d_out, int out_size) {
    const float* in1 = (const float*)d_in[0];
    const float* in2 = (const float*)d_in[1];
    float* out = (float*)d_out;

    cudaFuncSetAttribute(Correlation_36730560316063_kernel,
                         cudaFuncAttributeMaxDynamicSharedMemorySize,
                         SMEM_BYTES);

    dim3 grid(D41, HH, 4);
    Correlation_36730560316063_kernel<<<grid, 128, SMEM_BYTES>>>(in1, in2, out);
}

// round 2
// speedup vs baseline: 1.7678x; 1.7678x over previous
#include <cuda_runtime.h>

// Correlation layer: out[b, i*41+j, y, x] =
//   (1/576) * sum_c in1[b,c,y,x] * in2[b,c, y-2*(j-10), x-2*(i-10)]
// in1, in2: [4, 64, 96, 160] fp32;  out: [4, 1681, 96, 160] fp32.
//
// CTA = (j, y, b). Channel-split smem (2 passes of 32 channels):
//   sA: 32x160 in1 row chunk, sB: 32x240 zero-padded in2 row chunk.
//   50 KB smem -> 4 CTAs/SM (16 warps) vs 2 before.
// 128 threads = 16 x-groups (5 f32-pairs) x 8 i-groups (6 displacements).
// Packed fp32 math via fma.rn.f32x2 (SASS FFMA2).

#define D41 41
#define HH 96
#define WW 160
#define CC 64
#define CH 32                        // channels per pass

#define SA_FLOATS (CH * WW)          // 5120
#define SB_FLOATS (CH * 240)         // 7680
#define SMEM_BYTES ((SA_FLOATS + SB_FLOATS) * 4)   // 51200

__device__ __forceinline__ void fma2(unsigned long long& d,
                                     unsigned long long a,
                                     unsigned long long b) {
    asm("fma.rn.f32x2 %0, %1, %2, %0;" : "+l"(d) : "l"(a), "l"(b));
}

__device__ __forceinline__ unsigned long long lds2(const float* p) {
    return *reinterpret_cast<const unsigned long long*>(p);
}

// Accumulate 32 channels into acc.
// FAST: i-group fully in range, shifts = 5-ii.
// !FAST: i0 == 36 pattern, shifts = {4,3,2,1,0,0}.
template<bool FAST>
__device__ __forceinline__ void corr_accum32(
    const float* __restrict__ sA, const float* __restrict__ sB,
    int p0, int qb, unsigned long long acc[6][5])
{
    const float* Ar = sA + 2 * p0;
    const float* Br = sB + 2 * qb;

#pragma unroll 2
    for (int c = 0; c < CH; ++c) {
        unsigned long long a[5];
#pragma unroll
        for (int k = 0; k < 5; ++k) a[k] = lds2(Ar + c * WW + 2 * k);
        unsigned long long bw[10];
#pragma unroll
        for (int t = 0; t < 10; ++t) bw[t] = lds2(Br + c * 240 + 2 * t);
#pragma unroll
        for (int ii = 0; ii < 6; ++ii) {
            const int sh = FAST ? (5 - ii) : (ii < 4 ? 4 - ii : 0);
#pragma unroll
            for (int k = 0; k < 5; ++k)
                fma2(acc[ii][k], a[k], bw[sh + k]);
        }
    }
}

extern __shared__ float smem[];

__global__ void __launch_bounds__(128, 4)
Correlation_36730560316063_kernel(const float* __restrict__ in1,
                                  const float* __restrict__ in2,
                                  float* __restrict__ out)
{
    const int j = blockIdx.x;      // dy index
    const int y = blockIdx.y;
    const int b = blockIdx.z;
    const int tid = threadIdx.x;

    const int dy = 2 * (j - 10);
    const int y2 = y - dy;

    const int obase = ((b * (D41 * D41) + j) * HH + y) * WW;
    const int ostride_i = D41 * HH * WW;

    if (y2 < 0 || y2 >= HH) {
        // whole (b, y, j) slab is zero (output is poisoned: must write zeros)
        const float4 z = make_float4(0.f, 0.f, 0.f, 0.f);
        for (int idx = tid; idx < D41 * (WW / 4); idx += 128) {
            int i = idx / (WW / 4);
            int v = idx % (WW / 4);
            *reinterpret_cast<float4*>(out + obase + i * ostride_i + v * 4) = z;
        }
        return;
    }

    float* sA = smem;               // [32][160]
    float* sB = smem + SA_FLOATS;   // [32][240]: [0,60)=0, [60,220)=data, [220,240)=0

    // zero pads of sB once (rows are overwritten in place per pass; pads persist)
    {
        const float4 z = make_float4(0.f, 0.f, 0.f, 0.f);
        for (int idx = tid; idx < CH * 20; idx += 128) {
            int c = idx / 20, v = idx % 20;
            int off = (v < 15) ? v * 4 : 220 + (v - 15) * 4;
            *reinterpret_cast<float4*>(sB + c * 240 + off) = z;
        }
    }

    const int xg = tid & 15;        // 16 x-groups
    const int ig = tid >> 4;        // 8 i-groups
    const int p0 = xg * 5;          // first output x-pair (x = 2*p0)
    const int i0 = ig * 6;          // first displacement index

    unsigned long long acc[6][5];
#pragma unroll
    for (int ii = 0; ii < 6; ++ii)
#pragma unroll
        for (int k = 0; k < 5; ++k) acc[ii][k] = 0ULL;

#pragma unroll 1
    for (int half = 0; half < 2; ++half) {
        const int cbase = half * CH;
        // sA <- in1[b, cbase:cbase+32, y, :]
        {
            const float* a_src = in1 + (((b * CC + cbase)) * HH + y) * WW;
            for (int idx = tid; idx < CH * (WW / 4); idx += 128) {
                int c = idx / (WW / 4), v = idx % (WW / 4);
                *reinterpret_cast<float4*>(sA + c * WW + v * 4) =
                    *reinterpret_cast<const float4*>(a_src + c * HH * WW + v * 4);
            }
        }
        // sB data <- in2[b, cbase:cbase+32, y2, :]
        {
            const float* b_src = in2 + (((b * CC + cbase)) * HH + y2) * WW;
            for (int idx = tid; idx < CH * (WW / 4); idx += 128) {
                int c = idx / (WW / 4), v = idx % (WW / 4);
                *reinterpret_cast<float4*>(sB + c * 240 + 60 + v * 4) =
                    *reinterpret_cast<const float4*>(b_src + c * HH * WW + v * 4);
            }
        }
        __syncthreads();

        if (ig < 6) {
            const int qb = p0 + 35 - i0;       // window [qb, qb+10)
            corr_accum32<true>(sA, sB, p0, qb, acc);
        } else if (ig == 6) {                  // i = 36..41 (41 clamped)
            const int qb = p0;                 // window [p0, p0+9)
            corr_accum32<false>(sA, sB, p0, qb, acc);
        }
        __syncthreads();
    }

    if (ig == 7) return;                       // nothing to store

    const float scale = 1.0f / 576.0f;
    const int NI = (ig < 6) ? 6 : 5;
#pragma unroll
    for (int ii = 0; ii < 6; ++ii) {
        if (ii >= NI) break;
#pragma unroll
        for (int k = 0; k < 5; ++k) {
            unsigned long long v = acc[ii][k];
            float lo = __uint_as_float((unsigned)(v & 0xffffffffu));
            float hi = __uint_as_float((unsigned)(v >> 32));
            float2 r;
            r.x = lo * scale;
            r.y = hi * scale;
            *reinterpret_cast<float2*>(out + obase + (i0 + ii) * ostride_i
                                       + 2 * (p0 + k)) = r;
        }
    }
}

extern "C" void kernel_launch(void* const* d_in, const int* in_sizes, int n_in,
                              void* d_out, int out_size) {
    const float* in1 = (const float*)d_in[0];
    const float* in2 = (const float*)d_in[1];
    float* out = (float*)d_out;

    cudaFuncSetAttribute(Correlation_36730560316063_kernel,
                         cudaFuncAttributeMaxDynamicSharedMemorySize,
                         SMEM_BYTES);

    dim3 grid(D41, HH, 4);
    Correlation_36730560316063_kernel<<<grid, 128, SMEM_BYTES>>>(in1, in2, out);
}

// round 3
// speedup vs baseline: 1.7702x; 1.0014x over previous
#include <cuda_runtime.h>

// Correlation layer: out[b, i*41+j, y, x] =
//   (1/576) * sum_c in1[b,c,y,x] * in2[b,c, y-2*(j-10), x-2*(i-10)]
// in1, in2: [4, 64, 96, 160] fp32;  out: [4, 1681, 96, 160] fp32.
//
// CTA = (j, y, b). Channel-split smem (2 passes of 32 channels):
//   sA: 32x160 in1 row chunk, sB: 32x240 zero-padded in2 row chunk.
//   50 KB smem -> 4 CTAs/SM (16 warps) vs 2 before.
// 128 threads = 16 x-groups (5 f32-pairs) x 8 i-groups (6 displacements).
// Packed fp32 math via fma.rn.f32x2 (SASS FFMA2).

#define D41 41
#define HH 96
#define WW 160
#define CC 64
#define CH 32                        // channels per pass

#define SA_FLOATS (CH * WW)          // 5120
#define SB_FLOATS (CH * 240)         // 7680
#define SMEM_BYTES ((SA_FLOATS + SB_FLOATS) * 4)   // 51200

__device__ __forceinline__ void fma2(unsigned long long& d,
                                     unsigned long long a,
                                     unsigned long long b) {
    asm("fma.rn.f32x2 %0, %1, %2, %0;" : "+l"(d) : "l"(a), "l"(b));
}

__device__ __forceinline__ unsigned long long lds2(const float* p) {
    return *reinterpret_cast<const unsigned long long*>(p);
}

// Accumulate 32 channels into acc.
// FAST: i-group fully in range, shifts = 5-ii.
// !FAST: i0 == 36 pattern, shifts = {4,3,2,1,0,0}.
template<bool FAST>
__device__ __forceinline__ void corr_accum32(
    const float* __restrict__ sA, const float* __restrict__ sB,
    int p0, int qb, unsigned long long acc[6][5])
{
    const float* Ar = sA + 2 * p0;
    const float* Br = sB + 2 * qb;

#pragma unroll 2
    for (int c = 0; c < CH; ++c) {
        unsigned long long a[5];
#pragma unroll
        for (int k = 0; k < 5; ++k) a[k] = lds2(Ar + c * WW + 2 * k);
        unsigned long long bw[10];
#pragma unroll
        for (int t = 0; t < 10; ++t) bw[t] = lds2(Br + c * 240 + 2 * t);
#pragma unroll
        for (int ii = 0; ii < 6; ++ii) {
            const int sh = FAST ? (5 - ii) : (ii < 4 ? 4 - ii : 0);
#pragma unroll
            for (int k = 0; k < 5; ++k)
                fma2(acc[ii][k], a[k], bw[sh + k]);
        }
    }
}

extern __shared__ float smem[];

__global__ void __launch_bounds__(128, 4)
Correlation_36730560316063_kernel(const float* __restrict__ in1,
                                  const float* __restrict__ in2,
                                  float* __restrict__ out)
{
    const int j = blockIdx.x;      // dy index
    const int y = blockIdx.y;
    const int b = blockIdx.z;
    const int tid = threadIdx.x;

    const int dy = 2 * (j - 10);
    const int y2 = y - dy;

    const int obase = ((b * (D41 * D41) + j) * HH + y) * WW;
    const int ostride_i = D41 * HH * WW;

    if (y2 < 0 || y2 >= HH) {
        // whole (b, y, j) slab is zero (output is poisoned: must write zeros)
        const float4 z = make_float4(0.f, 0.f, 0.f, 0.f);
        for (int idx = tid; idx < D41 * (WW / 4); idx += 128) {
            int i = idx / (WW / 4);
            int v = idx % (WW / 4);
            *reinterpret_cast<float4*>(out + obase + i * ostride_i + v * 4) = z;
        }
        return;
    }

    float* sA = smem;               // [32][160]
    float* sB = smem + SA_FLOATS;   // [32][240]: [0,60)=0, [60,220)=data, [220,240)=0

    // zero pads of sB once (rows are overwritten in place per pass; pads persist)
    {
        const float4 z = make_float4(0.f, 0.f, 0.f, 0.f);
        for (int idx = tid; idx < CH * 20; idx += 128) {
            int c = idx / 20, v = idx % 20;
            int off = (v < 15) ? v * 4 : 220 + (v - 15) * 4;
            *reinterpret_cast<float4*>(sB + c * 240 + off) = z;
        }
    }

    const int xg = tid & 15;        // 16 x-groups
    const int ig = tid >> 4;        // 8 i-groups
    const int p0 = xg * 5;          // first output x-pair (x = 2*p0)
    const int i0 = ig * 6;          // first displacement index

    unsigned long long acc[6][5];
#pragma unroll
    for (int ii = 0; ii < 6; ++ii)
#pragma unroll
        for (int k = 0; k < 5; ++k) acc[ii][k] = 0ULL;

#pragma unroll 1
    for (int half = 0; half < 2; ++half) {
        const int cbase = half * CH;
        // sA <- in1[b, cbase:cbase+32, y, :]
        {
            const float* a_src = in1 + (((b * CC + cbase)) * HH + y) * WW;
            for (int idx = tid; idx < CH * (WW / 4); idx += 128) {
                int c = idx / (WW / 4), v = idx % (WW / 4);
                *reinterpret_cast<float4*>(sA + c * WW + v * 4) =
                    *reinterpret_cast<const float4*>(a_src + c * HH * WW + v * 4);
            }
        }
        // sB data <- in2[b, cbase:cbase+32, y2, :]
        {
            const float* b_src = in2 + (((b * CC + cbase)) * HH + y2) * WW;
            for (int idx = tid; idx < CH * (WW / 4); idx += 128) {
                int c = idx / (WW / 4), v = idx % (WW / 4);
                *reinterpret_cast<float4*>(sB + c * 240 + 60 + v * 4) =
                    *reinterpret_cast<const float4*>(b_src + c * HH * WW + v * 4);
            }
        }
        __syncthreads();

        if (ig < 6) {
            const int qb = p0 + 35 - i0;       // window [qb, qb+10)
            corr_accum32<true>(sA, sB, p0, qb, acc);
        } else if (ig == 6) {                  // i = 36..41 (41 clamped)
            const int qb = p0;                 // window [p0, p0+9)
            corr_accum32<false>(sA, sB, p0, qb, acc);
        }
        __syncthreads();
    }

    if (ig == 7) return;                       // nothing to store

    const float scale = 1.0f / 576.0f;
    const int NI = (ig < 6) ? 6 : 5;
#pragma unroll
    for (int ii = 0; ii < 6; ++ii) {
        if (ii >= NI) break;
#pragma unroll
        for (int k = 0; k < 5; ++k) {
            unsigned long long v = acc[ii][k];
            float lo = __uint_as_float((unsigned)(v & 0xffffffffu));
            float hi = __uint_as_float((unsigned)(v >> 32));
            float2 r;
            r.x = lo * scale;
            r.y = hi * scale;
            *reinterpret_cast<float2*>(out + obase + (i0 + ii) * ostride_i
                                       + 2 * (p0 + k)) = r;
        }
    }
}

extern "C" void kernel_launch(void* const* d_in, const int* in_sizes, int n_in,
                              void* d_out, int out_size) {
    const float* in1 = (const float*)d_in[0];
    const float* in2 = (const float*)d_in[1];
    float* out = (float*)d_out;

    cudaFuncSetAttribute(Correlation_36730560316063_kernel,
                         cudaFuncAttributeMaxDynamicSharedMemorySize,
                         SMEM_BYTES);

    dim3 grid(D41, HH, 4);
    Correlation_36730560316063_kernel<<<grid, 128, SMEM_BYTES>>>(in1, in2, out);
}